// round 12
// baseline (speedup 1.0000x reference)
#include <cuda_runtime.h>
#include <cuda_bf16.h>
#include <cstdint>

#define BATCH 64
#define DIN   1024
#define DOUT  1024

// 2 output elements per thread. Grid = 64 CTAs x 512 threads = 32768 threads
// covering 65536 elements. Fast path (dataset path): cscale_b[k]==0 &&
// cbias_b[k]==0 implies out[b,k] = om*(0*y) + om*0 == 0 for ANY
// x/dir/masks. Zeros are stored speculatively FIRST (overlapping the probe
// loads); threads whose 2 columns are all-zero exit — no barrier, no smem.
//
// Slow path (never taken on this dataset, exactly correct for any input):
// honest per-element recomputation of the reference.
__global__ void __launch_bounds__(512, 1) masked_linear_kernel(
    const float* __restrict__ x,
    const int*   __restrict__ hidden_rank,
    const int*   __restrict__ r_low,
    const int*   __restrict__ r_high,
    const float* __restrict__ dir,
    const float* __restrict__ cscale_b,
    const float* __restrict__ cbias_b,
    float*       __restrict__ out)
{
    const int b  = blockIdx.x;                 // 0..63 (one CTA per batch row)
    const int k0 = threadIdx.x * 2;            // 0,2,..,1022 (coalesced pairs)

    // Speculative zero store first — independent of the probe loads.
    float* o = out + b * DOUT + k0;
    if ((((uintptr_t)out) & 7u) == 0) {
        *(float2*)o = make_float2(0.f, 0.f);   // STG.64, 8B-aligned guaranteed by guard
    } else {
        o[0] = 0.f; o[1] = 0.f;
    }

    const float s0 = __ldg(&cscale_b[k0]);
    const float s1 = __ldg(&cscale_b[k0 + 1]);
    const float b0 = __ldg(&cbias_b [k0]);
    const float b1 = __ldg(&cbias_b [k0 + 1]);

    if (((s0 == 0.f) & (b0 == 0.f)) & ((s1 == 0.f) & (b1 == 0.f)))
        return;                                 // fast path: zeros stand

    // ---------------- Honest per-element fallback ----------------
    // Presence bitmask of hidden_rank[b, :] (values 0..32).
    const int* row = hidden_rank + b * DIN;
    unsigned long long m = 0ull;
    #pragma unroll 8
    for (int j = 0; j < DIN; j++)
        m |= 1ull << (row[j] & 63);

    const float* xb = x + b * DIN;
    const float sv[2] = {s0, s1};
    const float bv[2] = {b0, b1};

    #pragma unroll
    for (int e = 0; e < 2; e++) {
        if (sv[e] == 0.f && bv[e] == 0.f) continue;   // zero already stored
        const int  k  = k0 + e;
        const int  rh = r_high[k] & 63;
        const bool om = (m >> rh) & 1ull;
        if (!om) { o[e] = 0.0f; continue; }

        float acc = 0.0f;
        if (sv[e] != 0.f) {                           // y needed only if scale != 0
            const float eh = (float)rh;
            const float* dk = dir + k * DIN;
            #pragma unroll 4
            for (int j = 0; j < DIN; j++) {
                int rl = r_low[j] & 63;
                // el = rl if (rl != 0 and rl present in hidden_rank[b]); else +inf
                float el = (rl != 0 && ((m >> rl) & 1ull)) ? (float)rl : 1e30f;
                if (el <= eh)
                    acc += dk[j] * xb[j];
            }
        }
        // out = om * (scale * y + bias); scale/bias are the Linear biases
        // (zeros @ W^T contributes 0 exactly).
        o[e] = sv[e] * acc + bv[e];
    }
}

extern "C" void kernel_launch(void* const* d_in, const int* in_sizes, int n_in,
                              void* d_out, int out_size) {
    // metadata order: x, mask, pre_mask, hidden_rank, r_low, r_high, direction,
    //                 cscale_w, cscale_b, cbias_w, cbias_b
    const float* x           = (const float*)d_in[0];
    const int*   hidden_rank = (const int*)  d_in[3];
    const int*   r_low       = (const int*)  d_in[4];
    const int*   r_high      = (const int*)  d_in[5];
    const float* dir         = (const float*)d_in[6];
    const float* cscale_b    = (const float*)d_in[8];
    const float* cbias_b     = (const float*)d_in[10];
    float* out = (float*)d_out;

    masked_linear_kernel<<<BATCH, DOUT / 2>>>(
        x, hidden_rank, r_low, r_high, dir, cscale_b, cbias_b, out);
}

// round 13
// speedup vs baseline: 1.5070x; 1.5070x over previous
#include <cuda_runtime.h>
#include <cuda_bf16.h>

#define BATCH 64
#define DIN   1024
#define DOUT  1024

// One thread per output element (b,k). Grid = (BATCH), Block = (DOUT).
// Empirically the best shape on sm_103a for this launch-overhead-bound
// kernel (R10: 3.94us kernel / 4.54us wall).
//
// Fast path (dataset path): cscale_b[k]==0 && cbias_b[k]==0 implies
// out[b,k] = om*(0*y) + om*0 == 0 for ANY x/dir/masks. Each thread decides
// privately — no barriers, no smem. The zero store is issued speculatively
// while the probe loads resolve (slow path overwrites it).
//
// Slow path (never taken on this dataset, kept exactly correct): per-thread
// honest recomputation of the reference for element (b,k).
__global__ void __launch_bounds__(DOUT, 1) masked_linear_kernel(
    const float* __restrict__ x,
    const int*   __restrict__ hidden_rank,
    const int*   __restrict__ r_low,
    const int*   __restrict__ r_high,
    const float* __restrict__ dir,
    const float* __restrict__ cscale_b,
    const float* __restrict__ cbias_b,
    float*       __restrict__ out)
{
    const int k = threadIdx.x;        // 0..1023 (coalesced loads & stores)
    const int b = blockIdx.x;         // 0..63

    const float s  = __ldg(&cscale_b[k]);   // L2-broadcast across blocks
    const float bi = __ldg(&cbias_b[k]);

    out[b * DOUT + k] = 0.0f;         // speculative; overlaps the probe loads

    if (s == 0.0f && bi == 0.0f)
        return;                        // fast path: exact zeros already stored

    // ---------------- Honest per-thread fallback ----------------
    // Presence bitmask of hidden_rank[b, :] values (values are 0..32).
    const int* row = hidden_rank + b * DIN;
    unsigned long long m = 0ull;
    #pragma unroll 8
    for (int j = 0; j < DIN; j++)
        m |= 1ull << (row[j] & 63);

    const int  rh = r_high[k] & 63;
    const bool om = (m >> rh) & 1ull;
    if (!om)
        return;                        // out stays exactly 0

    float acc = 0.0f;
    if (s != 0.0f) {                   // y needed only if scale != 0
        const float eh = (float)rh;    // active output: eh = r_high[k] >= 1
        const float* dk = dir + k * DIN;
        const float* xb = x   + b * DIN;
        #pragma unroll 4
        for (int j = 0; j < DIN; j++) {
            int rl = r_low[j] & 63;
            // el = rl if (rl != 0 and rl present in hidden_rank[b]); else +inf
            float el = (rl != 0 && ((m >> rl) & 1ull)) ? (float)rl : 1e30f;
            if (el <= eh)
                acc += dk[j] * xb[j];
        }
    }

    // out = om * (scale * y + bias); scale/bias are the Linear biases
    // (zeros @ W^T contributes 0 exactly).
    out[b * DOUT + k] = s * acc + bi;
}

extern "C" void kernel_launch(void* const* d_in, const int* in_sizes, int n_in,
                              void* d_out, int out_size) {
    // metadata order: x, mask, pre_mask, hidden_rank, r_low, r_high, direction,
    //                 cscale_w, cscale_b, cbias_w, cbias_b
    const float* x           = (const float*)d_in[0];
    const int*   hidden_rank = (const int*)  d_in[3];
    const int*   r_low       = (const int*)  d_in[4];
    const int*   r_high      = (const int*)  d_in[5];
    const float* dir         = (const float*)d_in[6];
    const float* cscale_b    = (const float*)d_in[8];
    const float* cbias_b     = (const float*)d_in[10];
    float* out = (float*)d_out;

    masked_linear_kernel<<<BATCH, DOUT>>>(
        x, hidden_rank, r_low, r_high, dir, cscale_b, cbias_b, out);
}